// round 4
// baseline (speedup 1.0000x reference)
#include <cuda_runtime.h>
#include <math.h>

typedef unsigned long long ull;

#define B_  8
#define S_  4096
#define D_  256
#define F_  512
#define E_  8
#define N_  (B_*S_)

#define MTILE  64
#define XS_LD  264
#define HS_LD  136
#define W1S_LD 136
#define W2S_LD 264
#define WS_FLOATS 8704   // max(64*136, 32*264)
#define SMEM_FLOATS (MTILE*XS_LD + MTILE*HS_LD + WS_FLOATS)

__device__ float g_partial[B_*32*D_];
__device__ int   g_re[B_*2];
__device__ float g_rw[B_*2];

__device__ __forceinline__ ull pack2(float x, float y){
  ull r; asm("mov.b64 %0, {%1, %2};" : "=l"(r) : "f"(x), "f"(y)); return r;
}
__device__ __forceinline__ float2 unpack2(ull v){
  float2 f; asm("mov.b64 {%0, %1}, %2;" : "=f"(f.x), "=f"(f.y) : "l"(v)); return f;
}
#define FFMA2(acc, a, b) asm("fma.rn.f32x2 %0, %1, %2, %0;" : "+l"(acc) : "l"(a), "l"(b))

__device__ __forceinline__ float gelu_exact(float v){
  return 0.5f * v * (1.0f + erff(v * 0.70710678118654752f));
}

// ---------------- Kernel 1: per-batch column partial sums over S ----------------
__global__ void colsum_kernel(const float* __restrict__ x){
  int b     = blockIdx.x >> 5;
  int chunk = blockIdx.x & 31;
  int d     = threadIdx.x;
  const float* xp = x + ((size_t)(b*S_ + chunk*128))*D_ + d;
  float s = 0.f;
  #pragma unroll 4
  for (int i = 0; i < 128; i++) s += xp[(size_t)i * D_];
  g_partial[(b*32 + chunk)*D_ + d] = s;
}

// ---------------- Kernel 2: router (tiny) ----------------
__global__ void router_kernel(const float* __restrict__ Wr, const float* __restrict__ br){
  __shared__ float smean[B_][D_];
  __shared__ float slog[B_][E_];
  int tid = threadIdx.x;
  for (int idx = tid; idx < B_*D_; idx += 256){
    int b = idx >> 8, d = idx & 255;
    float s = 0.f;
    for (int c = 0; c < 32; c++) s += g_partial[(b*32 + c)*D_ + d];
    smean[b][d] = s * (1.0f / (float)S_);
  }
  __syncthreads();
  if (tid < B_*E_){
    int b = tid >> 3, e = tid & 7;
    float acc = br[e];
    for (int d = 0; d < D_; d++) acc += smean[b][d] * Wr[d*E_ + e];
    slog[b][e] = acc;
  }
  __syncthreads();
  if (tid == 0){
    float rw[B_][E_];
    for (int b = 0; b < B_; b++){
      float m = -1e30f;
      for (int e = 0; e < E_; e++) m = fmaxf(m, slog[b][e]);
      float s = 0.f;
      for (int e = 0; e < E_; e++){ float v = expf(slog[b][e]-m); rw[b][e] = v; s += v; }
      for (int e = 0; e < E_; e++) rw[b][e] /= s;
    }
    const float capacity = ceilf((float)N_ * 1.25f / (float)E_);  // 5120
    float scale[E_];
    for (int e = 0; e < E_; e++){
      float load = 0.f;
      for (int b = 0; b < B_; b++) load += rw[b][e];
      load *= (float)(N_ / B_);
      scale[e] = (load > capacity) ? (capacity / load) : 1.0f;
    }
    for (int b = 0; b < B_; b++){
      float t[E_]; float m = -1e30f;
      for (int e = 0; e < E_; e++){ t[e] = rw[b][e]*scale[e]; m = fmaxf(m, t[e]); }
      float s = 0.f;
      for (int e = 0; e < E_; e++){ t[e] = expf(t[e]-m); s += t[e]; }
      for (int e = 0; e < E_; e++) t[e] /= s;
      int e1 = 0; float v1 = t[0];
      for (int e = 1; e < E_; e++) if (t[e] > v1){ v1 = t[e]; e1 = e; }
      int e2 = -1; float v2 = -1e30f;
      for (int e = 0; e < E_; e++){ if (e == e1) continue; if (t[e] > v2){ v2 = t[e]; e2 = e; } }
      float ex = expf(v2 - v1);
      float w1 = 1.0f/(1.0f+ex), w2 = ex/(1.0f+ex);
      g_re[b*2]   = e1; g_re[b*2+1] = e2;
      g_rw[b*2]   = w1; g_rw[b*2+1] = w2;
    }
  }
}

// ---------------- Kernel 3: fused 2-expert FFN + combine + residual + LN ----------------
__global__ void __launch_bounds__(256, 1)
moe_ffn_kernel(const float* __restrict__ x,
               const float* __restrict__ W1, const float* __restrict__ b1,
               const float* __restrict__ W2, const float* __restrict__ b2,
               const float* __restrict__ gamma, const float* __restrict__ beta,
               float* __restrict__ out)
{
  extern __shared__ float sm[];
  float* Xs = sm;                       // [64][XS_LD]
  float* Hs = Xs + MTILE*XS_LD;         // [64][HS_LD]
  float* Ws = Hs + MTILE*HS_LD;         // shared W1/W2 slab buffer

  const int tid = threadIdx.x;
  const int tx  = tid & 15;
  const int ty  = tid >> 4;
  const int n0  = blockIdx.x * MTILE;
  const int b   = n0 >> 12;             // 4096 tokens per batch
  const int r0  = ty * 4;
  const int c1  = tx * 8;               // GEMM1 column base (within F-chunk of 128)
  const int c2  = tx * 16;              // GEMM2 column base (within D=256)

  // Load X tile [64][256]
  {
    const float4* xg = reinterpret_cast<const float4*>(x + (size_t)n0 * D_);
    for (int i = tid; i < MTILE*(D_/4); i += 256){
      int r = i >> 6, c4 = i & 63;
      *reinterpret_cast<float4*>(&Xs[r*XS_LD + c4*4]) = xg[r*(D_/4) + c4];
    }
  }

  ull yacc[4][8];
  #pragma unroll
  for (int i = 0; i < 4; i++)
    #pragma unroll
    for (int j = 0; j < 8; j++) yacc[i][j] = 0ull;

  __syncthreads();

  #pragma unroll 1
  for (int ei = 0; ei < 2; ei++){
    const int   e  = g_re[b*2 + ei];
    const float we = g_rw[b*2 + ei];
    const float* W1e = W1 + (size_t)e * D_ * F_;
    const float* W2e = W2 + (size_t)e * F_ * D_;

    #pragma unroll 1
    for (int fc = 0; fc < 4; fc++){
      const int f0 = fc * 128;

      float bb1[8];
      #pragma unroll
      for (int j = 0; j < 8; j++) bb1[j] = b1[e*F_ + f0 + c1 + j];

      ull hacc[4][4];
      #pragma unroll
      for (int i = 0; i < 4; i++)
        #pragma unroll
        for (int j = 0; j < 4; j++) hacc[i][j] = 0ull;

      // ---- GEMM1: H[64][128] = X[64][256] @ W1[e][:, f0:f0+128] ----
      #pragma unroll 1
      for (int ks = 0; ks < 4; ks++){
        const float4* wg = reinterpret_cast<const float4*>(W1e + (size_t)(ks*64)*F_ + f0);
        for (int i = tid; i < 64*32; i += 256){
          int r = i >> 5, c4 = i & 31;
          *reinterpret_cast<float4*>(&Ws[r*W1S_LD + c4*4]) = wg[r*(F_/4) + c4];
        }
        __syncthreads();
        const float* xrow = &Xs[r0*XS_LD + ks*64];
        #pragma unroll 4
        for (int kk = 0; kk < 64; kk++){
          ull a2[4];
          #pragma unroll
          for (int i = 0; i < 4; i++){
            float av = xrow[i*XS_LD + kk];
            a2[i] = pack2(av, av);
          }
          const ull* bp = reinterpret_cast<const ull*>(&Ws[kk*W1S_LD + c1]);
          ull bv[4];
          #pragma unroll
          for (int j = 0; j < 4; j++) bv[j] = bp[j];
          #pragma unroll
          for (int i = 0; i < 4; i++)
            #pragma unroll
            for (int j = 0; j < 4; j++)
              FFMA2(hacc[i][j], a2[i], bv[j]);
        }
        __syncthreads();
      }

      // ---- epilogue1: GELU(h + b1) * we -> Hs ----
      #pragma unroll
      for (int i = 0; i < 4; i++){
        #pragma unroll
        for (int j = 0; j < 4; j++){
          float2 hv = unpack2(hacc[i][j]);
          float h0 = we * gelu_exact(hv.x + bb1[2*j]);
          float h1 = we * gelu_exact(hv.y + bb1[2*j+1]);
          *reinterpret_cast<float2*>(&Hs[(r0+i)*HS_LD + c1 + 2*j]) = make_float2(h0, h1);
        }
      }
      __syncthreads();

      // ---- GEMM2: Y[64][256] += Hs[64][128] @ W2[e][f0:f0+128][:] ----
      #pragma unroll 1
      for (int ks = 0; ks < 4; ks++){
        const float4* wg = reinterpret_cast<const float4*>(W2e + (size_t)(f0 + ks*32)*D_);
        for (int i = tid; i < 32*64; i += 256){
          int r = i >> 6, c4 = i & 63;
          *reinterpret_cast<float4*>(&Ws[r*W2S_LD + c4*4]) = wg[r*(D_/4) + c4];
        }
        __syncthreads();
        const float* hrow = &Hs[r0*HS_LD + ks*32];
        #pragma unroll 4
        for (int kk = 0; kk < 32; kk++){
          ull a2[4];
          #pragma unroll
          for (int i = 0; i < 4; i++){
            float av = hrow[i*HS_LD + kk];
            a2[i] = pack2(av, av);
          }
          const ull* bp = reinterpret_cast<const ull*>(&Ws[kk*W2S_LD + c2]);
          ull bv[8];
          #pragma unroll
          for (int j = 0; j < 8; j++) bv[j] = bp[j];
          #pragma unroll
          for (int i = 0; i < 4; i++)
            #pragma unroll
            for (int j = 0; j < 8; j++)
              FFMA2(yacc[i][j], a2[i], bv[j]);
        }
        __syncthreads();
      }
    }

    // ---- add we * b2[e] ----
    {
      ull we2 = pack2(we, we);
      const ull* b2p = reinterpret_cast<const ull*>(b2 + e*D_ + c2);
      #pragma unroll
      for (int j = 0; j < 8; j++){
        ull bvv = b2p[j];
        #pragma unroll
        for (int i = 0; i < 4; i++) FFMA2(yacc[i][j], we2, bvv);
      }
    }
  }

  // ---- residual + LayerNorm + store ----
  float gv[16], bev[16];
  {
    const float4* gp = reinterpret_cast<const float4*>(gamma + c2);
    const float4* bp = reinterpret_cast<const float4*>(beta  + c2);
    #pragma unroll
    for (int j4 = 0; j4 < 4; j4++){
      float4 g4 = gp[j4]; float4 b4 = bp[j4];
      gv[j4*4+0]=g4.x; gv[j4*4+1]=g4.y; gv[j4*4+2]=g4.z; gv[j4*4+3]=g4.w;
      bev[j4*4+0]=b4.x; bev[j4*4+1]=b4.y; bev[j4*4+2]=b4.z; bev[j4*4+3]=b4.w;
    }
  }
  #pragma unroll
  for (int i = 0; i < 4; i++){
    const int r = r0 + i;
    float v[16];
    float s = 0.f, ss = 0.f;
    #pragma unroll
    for (int j = 0; j < 8; j++){
      float2 yv = unpack2(yacc[i][j]);
      float v0 = yv.x + Xs[r*XS_LD + c2 + 2*j];
      float v1 = yv.y + Xs[r*XS_LD + c2 + 2*j + 1];
      v[2*j] = v0; v[2*j+1] = v1;
      s  += v0 + v1;
      ss += v0*v0 + v1*v1;
    }
    // reduce across the 16 lanes that share this row (lanes 0-15 or 16-31)
    #pragma unroll
    for (int off = 8; off >= 1; off >>= 1){
      s  += __shfl_xor_sync(0xffffffffu, s,  off);
      ss += __shfl_xor_sync(0xffffffffu, ss, off);
    }
    float mu  = s  * (1.0f / (float)D_);
    float var = ss * (1.0f / (float)D_) - mu*mu;
    float inv = rsqrtf(var + 1e-5f);
    float4 o[4];
    #pragma unroll
    for (int j4 = 0; j4 < 4; j4++){
      float* op = reinterpret_cast<float*>(&o[j4]);
      #pragma unroll
      for (int k = 0; k < 4; k++){
        int j = j4*4 + k;
        op[k] = (v[j] - mu)*inv*gv[j] + bev[j];
      }
    }
    float4* og = reinterpret_cast<float4*>(out + (size_t)(n0 + r)*D_ + c2);
    #pragma unroll
    for (int j4 = 0; j4 < 4; j4++) og[j4] = o[j4];
  }
}

extern "C" void kernel_launch(void* const* d_in, const int* in_sizes, int n_in,
                              void* d_out, int out_size){
  const float* x     = (const float*)d_in[0];
  const float* Wr    = (const float*)d_in[1];
  const float* br    = (const float*)d_in[2];
  const float* W1    = (const float*)d_in[3];
  const float* b1    = (const float*)d_in[4];
  const float* W2    = (const float*)d_in[5];
  const float* b2    = (const float*)d_in[6];
  const float* gamma = (const float*)d_in[7];
  const float* beta  = (const float*)d_in[8];
  float* out = (float*)d_out;

  cudaFuncSetAttribute(moe_ffn_kernel,
                       cudaFuncAttributeMaxDynamicSharedMemorySize,
                       SMEM_FLOATS * (int)sizeof(float));

  colsum_kernel<<<B_*32, 256>>>(x);
  router_kernel<<<1, 256>>>(Wr, br);
  moe_ffn_kernel<<<N_/MTILE, 256, SMEM_FLOATS*sizeof(float)>>>(
      x, W1, b1, W2, b2, gamma, beta, out);
}